// round 3
// baseline (speedup 1.0000x reference)
#include <cuda_runtime.h>
#include <cuda_bf16.h>
#include <cstdint>

#define N_NODES 50000
#define N_EDGES 800000
#define F_IN 64
#define HID 64
#define N_CLS 16

// Scratch (device globals — no allocation allowed). 16B-aligned for vector atomics.
__device__ __align__(16) float g_deg[N_NODES];
__device__ __align__(16) float g_sum1[N_NODES * HID];      // sum of x[src] per dst
__device__ __align__(16) float g_h[N_NODES * HID];         // layer-1 output
__device__ __align__(16) float g_p[N_NODES * N_CLS];       // h @ W2_l (pre-projected messages)
__device__ __align__(16) float g_sum2[N_NODES * N_CLS];    // sum of p[src] per dst

// ---------------------------------------------------------------------------
// Zero accumulators (vectorized)
// ---------------------------------------------------------------------------
__global__ void zero_k() {
    int i = blockIdx.x * blockDim.x + threadIdx.x;
    int stride = gridDim.x * blockDim.x;
    float4 z = make_float4(0.f, 0.f, 0.f, 0.f);
    float4* s1 = reinterpret_cast<float4*>(g_sum1);
    float4* s2 = reinterpret_cast<float4*>(g_sum2);
    float4* dg = reinterpret_cast<float4*>(g_deg);
    const int n1 = N_NODES * HID / 4;
    const int n2 = N_NODES * N_CLS / 4;
    const int nd = N_NODES / 4;
    for (int j = i; j < n1; j += stride) s1[j] = z;
    for (int j = i; j < n2; j += stride) s2[j] = z;
    for (int j = i; j < nd; j += stride) dg[j] = z;
}

// ---------------------------------------------------------------------------
// Scatter 1: sum1[dst] += x[src] (64 floats), deg[dst] += 1
// 16 threads per edge, float4 vector atomics (cc 9.0+ intrinsic).
// edge_index is int32 (JAX default x64-disabled downcasts int64 -> int32).
// ---------------------------------------------------------------------------
__global__ void scatter1_k(const float* __restrict__ x,
                           const int* __restrict__ ei) {
    long long tid = (long long)blockIdx.x * blockDim.x + threadIdx.x;
    int e = (int)(tid >> 4);
    int lane = (int)(tid & 15);
    if (e >= N_EDGES) return;
    int s = ei[e];
    int d = ei[N_EDGES + e];
    if ((unsigned)s >= N_NODES || (unsigned)d >= N_NODES) return;
    float4 v = reinterpret_cast<const float4*>(x + (size_t)s * HID)[lane];
    float4* dp = reinterpret_cast<float4*>(g_sum1 + (size_t)d * HID) + lane;
    atomicAdd(dp, v);
    if (lane == 0) atomicAdd(g_deg + d, 1.0f);
}

// ---------------------------------------------------------------------------
// Layer 1 fused: h = relu((sum1/deg) @ W1_l + x @ W1_r + b1); p = h @ W2_l
// Block = 128 threads = 4 warps; each warp owns 4 nodes per iteration.
// Lane j computes output columns {j, j+32}. Weights in shared memory.
// ---------------------------------------------------------------------------
__global__ void layer1_k(const float* __restrict__ x,
                         const float* __restrict__ W1l,
                         const float* __restrict__ b1,
                         const float* __restrict__ W1r,
                         const float* __restrict__ W2l) {
    __shared__ float sWl[64 * 64];
    __shared__ float sWr[64 * 64];
    __shared__ float sW2[64 * 16];
    __shared__ float sb1[64];
    __shared__ float sX[4][4][64];
    __shared__ float sM[4][4][64];   // mean rows; reused for h rows

    int tid = threadIdx.x, warp = tid >> 5, lane = tid & 31;
    for (int i = tid; i < 4096; i += 128) { sWl[i] = W1l[i]; sWr[i] = W1r[i]; }
    for (int i = tid; i < 1024; i += 128) sW2[i] = W2l[i];
    if (tid < 64) sb1[tid] = b1[tid];
    __syncthreads();

    for (int nb = (blockIdx.x * 4 + warp) * 4; nb < N_NODES; nb += gridDim.x * 16) {
        int nvalid = min(4, N_NODES - nb);
        for (int q = 0; q < nvalid; q++) {
            size_t r = (size_t)(nb + q) * 64;
            float invd = 1.0f / fmaxf(g_deg[nb + q], 1.0f);
            sX[warp][q][lane]      = x[r + lane];
            sX[warp][q][lane + 32] = x[r + lane + 32];
            sM[warp][q][lane]      = g_sum1[r + lane] * invd;
            sM[warp][q][lane + 32] = g_sum1[r + lane + 32] * invd;
        }
        __syncwarp();

        float a0[4], a1[4];
#pragma unroll
        for (int q = 0; q < 4; q++) { a0[q] = sb1[lane]; a1[q] = sb1[lane + 32]; }

#pragma unroll
        for (int k4 = 0; k4 < 64; k4 += 4) {
            float4 mv[4], xv[4];
#pragma unroll
            for (int q = 0; q < 4; q++) {
                mv[q] = *reinterpret_cast<const float4*>(&sM[warp][q][k4]);
                xv[q] = *reinterpret_cast<const float4*>(&sX[warp][q][k4]);
            }
#pragma unroll
            for (int kk = 0; kk < 4; kk++) {
                int k = k4 + kk;
                float wl0 = sWl[k * 64 + lane];
                float wl1 = sWl[k * 64 + lane + 32];
                float wr0 = sWr[k * 64 + lane];
                float wr1 = sWr[k * 64 + lane + 32];
#pragma unroll
                for (int q = 0; q < 4; q++) {
                    float m  = (kk == 0) ? mv[q].x : (kk == 1) ? mv[q].y : (kk == 2) ? mv[q].z : mv[q].w;
                    float xx = (kk == 0) ? xv[q].x : (kk == 1) ? xv[q].y : (kk == 2) ? xv[q].z : xv[q].w;
                    a0[q] = fmaf(m, wl0, a0[q]);
                    a0[q] = fmaf(xx, wr0, a0[q]);
                    a1[q] = fmaf(m, wl1, a1[q]);
                    a1[q] = fmaf(xx, wr1, a1[q]);
                }
            }
        }
        __syncwarp();   // all lanes done reading sM before overwrite

#pragma unroll
        for (int q = 0; q < 4; q++) {
            if (q < nvalid) {
                float h0 = fmaxf(a0[q], 0.f);
                float h1 = fmaxf(a1[q], 0.f);
                size_t r = (size_t)(nb + q) * 64;
                g_h[r + lane]      = h0;
                g_h[r + lane + 32] = h1;
                sM[warp][q][lane]      = h0;
                sM[warp][q][lane + 32] = h1;
            }
        }
        __syncwarp();

        {   // p = h @ W2_l : lane -> (node = lane>>3, col pair = lane&7)
            int n = lane >> 3, c0 = (lane & 7) * 2;
            if (n < nvalid) {
                float p0 = 0.f, p1 = 0.f;
#pragma unroll
                for (int k = 0; k < 64; k++) {
                    float hv = sM[warp][n][k];
                    p0 = fmaf(hv, sW2[k * 16 + c0], p0);
                    p1 = fmaf(hv, sW2[k * 16 + c0 + 1], p1);
                }
                size_t node = (size_t)(nb + n);
                g_p[node * 16 + c0]     = p0;
                g_p[node * 16 + c0 + 1] = p1;
            }
        }
        __syncwarp();
    }
}

// ---------------------------------------------------------------------------
// Scatter 2: sum2[dst] += p[src] (16 floats). 4 threads per edge, float4 atomics.
// ---------------------------------------------------------------------------
__global__ void scatter2_k(const int* __restrict__ ei) {
    long long tid = (long long)blockIdx.x * blockDim.x + threadIdx.x;
    int e = (int)(tid >> 2);
    int lane = (int)(tid & 3);
    if (e >= N_EDGES) return;
    int s = ei[e];
    int d = ei[N_EDGES + e];
    if ((unsigned)s >= N_NODES || (unsigned)d >= N_NODES) return;
    float4 v = reinterpret_cast<const float4*>(g_p + (size_t)s * 16)[lane];
    float4* dp = reinterpret_cast<float4*>(g_sum2 + (size_t)d * 16) + lane;
    atomicAdd(dp, v);
}

// ---------------------------------------------------------------------------
// Final: out = sum2/deg + h @ W2_r + b2
// Block = 128 = 4 warps, warp handles 4 nodes, lane -> (node, 2 classes)
// ---------------------------------------------------------------------------
__global__ void final_k(const float* __restrict__ W2r,
                        const float* __restrict__ b2,
                        float* __restrict__ out) {
    __shared__ float sW[64 * 16];
    __shared__ float sb[16];
    __shared__ float sh[4][4][64];
    int tid = threadIdx.x, warp = tid >> 5, lane = tid & 31;
    for (int i = tid; i < 1024; i += 128) sW[i] = W2r[i];
    if (tid < 16) sb[tid] = b2[tid];
    __syncthreads();

    int n = lane >> 3, c0 = (lane & 7) * 2;
    for (int nb = (blockIdx.x * 4 + warp) * 4; nb < N_NODES; nb += gridDim.x * 16) {
        int nvalid = min(4, N_NODES - nb);
        for (int q = 0; q < nvalid; q++) {
            size_t r = (size_t)(nb + q) * 64;
            sh[warp][q][lane]      = g_h[r + lane];
            sh[warp][q][lane + 32] = g_h[r + lane + 32];
        }
        __syncwarp();
        if (n < nvalid) {
            size_t node = (size_t)(nb + n);
            float invd = 1.0f / fmaxf(g_deg[node], 1.0f);
            float p0 = sb[c0]     + g_sum2[node * 16 + c0]     * invd;
            float p1 = sb[c0 + 1] + g_sum2[node * 16 + c0 + 1] * invd;
#pragma unroll
            for (int k = 0; k < 64; k++) {
                float hv = sh[warp][n][k];
                p0 = fmaf(hv, sW[k * 16 + c0], p0);
                p1 = fmaf(hv, sW[k * 16 + c0 + 1], p1);
            }
            out[node * 16 + c0]     = p0;
            out[node * 16 + c0 + 1] = p1;
        }
        __syncwarp();
    }
}

// ---------------------------------------------------------------------------
extern "C" void kernel_launch(void* const* d_in, const int* in_sizes, int n_in,
                              void* d_out, int out_size) {
    const float* x   = (const float*)d_in[0];
    const int*   ei  = (const int*)d_in[1];     // int32! (JAX x64 disabled)
    const float* W1l = (const float*)d_in[2];
    const float* b1  = (const float*)d_in[3];
    const float* W1r = (const float*)d_in[4];
    const float* W2l = (const float*)d_in[5];
    const float* b2  = (const float*)d_in[6];
    const float* W2r = (const float*)d_in[7];
    float* out = (float*)d_out;

    zero_k<<<592, 256>>>();
    scatter1_k<<<(N_EDGES * 16 + 255) / 256, 256>>>(x, ei);
    layer1_k<<<592, 128>>>(x, W1l, b1, W1r, W2l);
    scatter2_k<<<(N_EDGES * 4 + 255) / 256, 256>>>(ei);
    final_k<<<592, 128>>>(W2r, b2, out);
}